// round 4
// baseline (speedup 1.0000x reference)
#include <cuda_runtime.h>
#include <math.h>

#define NB   128
#define NHID 512
#define GATE_ELEMS (NB * NHID)   // 65536
#define NSPLIT 16
#define GEMM2_BLOCKS 16          // 8 j-tiles * 2 m-tiles (paired p/o, full-K)
#define TRACE_BLOCKS 32768

// ---------------- device scratch (no allocations allowed) ----------------
__device__ float d_part[NSPLIT][NB * 1024];  // split-K partials, 8 MB
__device__ float d_av  [GATE_ELEMS];         // 1 - g
__device__ float d_cgv [GATE_ELEMS];         // dg * delta_h
__device__ float d_crv [GATE_ELEMS];         // dr * g
__device__ float d_hv  [GATE_ELEMS];         // new h
__device__ int   d_cnt [256];                // per-block open counts (k_gates grid)

// ---------------------------------------------------------------------------
// Launch 1: split-K dual GEMM for g/r pre-activations.
//   partial[s][128,1024] = A[128,kchunk] @ W[1024,kchunk]^T
//   k halves (x | h_last), n halves (g | r). split s: half = s>>3, kb=(s&7)*64.
// BM=BN=64, BK=16, 256 threads, 4x4 register tile. grid=(16,2,16)=512 CTAs.
// ---------------------------------------------------------------------------
__global__ void __launch_bounds__(256) k_gemm1(
    const float* __restrict__ x, const float* __restrict__ h_last,
    const float* __restrict__ w_gx, const float* __restrict__ w_gh,
    const float* __restrict__ w_rx, const float* __restrict__ w_rh)
{
    __shared__ float As[16][68];
    __shared__ float Ws[16][68];

    const int tid  = threadIdx.x;
    const int n0   = blockIdx.x * 64;
    const int m0   = blockIdx.y * 64;
    const int s    = blockIdx.z;
    const int half = s >> 3;                 // 0: x-part, 1: h-part
    const int kb   = (s & 7) * 64;           // offset within the 512 half

    const bool g2 = (n0 >= 512);
    const int  j0 = g2 ? (n0 - 512) : n0;
    const float* A = half ? h_last : x;
    const float* W = g2 ? (half ? w_rh : w_rx) : (half ? w_gh : w_gx);
    float* outp    = d_part[s];

    const int lm  = tid & 63;
    const int lk4 = (tid >> 6) << 2;
    const int tx  = tid & 15;
    const int ty  = tid >> 4;

    const float* Aload = A + (m0 + lm) * 512 + kb + lk4;
    const float* Wload = W + (j0 + lm) * 512 + kb + lk4;

    float acc[4][4];
    #pragma unroll
    for (int i = 0; i < 4; i++)
        #pragma unroll
        for (int j = 0; j < 4; j++) acc[i][j] = 0.f;

    float4 av = *(const float4*)(Aload);
    float4 wv = *(const float4*)(Wload);

    for (int kt = 0; kt < 64; kt += 16) {
        __syncthreads();
        As[lk4 + 0][lm] = av.x; As[lk4 + 1][lm] = av.y;
        As[lk4 + 2][lm] = av.z; As[lk4 + 3][lm] = av.w;
        Ws[lk4 + 0][lm] = wv.x; Ws[lk4 + 1][lm] = wv.y;
        Ws[lk4 + 2][lm] = wv.z; Ws[lk4 + 3][lm] = wv.w;
        __syncthreads();

        if (kt + 16 < 64) {
            av = *(const float4*)(Aload + kt + 16);
            wv = *(const float4*)(Wload + kt + 16);
        }

        #pragma unroll
        for (int kk = 0; kk < 16; kk++) {
            const float4 a = *(const float4*)&As[kk][ty << 2];
            const float4 w = *(const float4*)&Ws[kk][tx << 2];
            acc[0][0] = fmaf(a.x, w.x, acc[0][0]);
            acc[0][1] = fmaf(a.x, w.y, acc[0][1]);
            acc[0][2] = fmaf(a.x, w.z, acc[0][2]);
            acc[0][3] = fmaf(a.x, w.w, acc[0][3]);
            acc[1][0] = fmaf(a.y, w.x, acc[1][0]);
            acc[1][1] = fmaf(a.y, w.y, acc[1][1]);
            acc[1][2] = fmaf(a.y, w.z, acc[1][2]);
            acc[1][3] = fmaf(a.y, w.w, acc[1][3]);
            acc[2][0] = fmaf(a.z, w.x, acc[2][0]);
            acc[2][1] = fmaf(a.z, w.y, acc[2][1]);
            acc[2][2] = fmaf(a.z, w.z, acc[2][2]);
            acc[2][3] = fmaf(a.z, w.w, acc[2][3]);
            acc[3][0] = fmaf(a.w, w.x, acc[3][0]);
            acc[3][1] = fmaf(a.w, w.y, acc[3][1]);
            acc[3][2] = fmaf(a.w, w.z, acc[3][2]);
            acc[3][3] = fmaf(a.w, w.w, acc[3][3]);
        }
    }

    #pragma unroll
    for (int i = 0; i < 4; i++) {
        float4 v = make_float4(acc[i][0], acc[i][1], acc[i][2], acc[i][3]);
        *(float4*)(outp + (m0 + (ty << 2) + i) * 1024 + n0 + (tx << 2)) = v;
    }
}

// ---------------------------------------------------------------------------
// Launch 2: gate epilogue — sum partials + bias, gate math, coefficients,
// e_b updates, per-block open counts. grid=256
// ---------------------------------------------------------------------------
__global__ void __launch_bounds__(256) k_gates(
    const float* __restrict__ h_last,
    const float* __restrict__ b_g, const float* __restrict__ b_r,
    const float* __restrict__ e_b_g, const float* __restrict__ e_b_r,
    float* __restrict__ out_h, float* __restrict__ out_ebg, float* __restrict__ out_ebr)
{
    __shared__ int scnt[8];
    const int idx = blockIdx.x * 256 + threadIdx.x;   // b*512 + j
    const int b = idx >> 9;
    const int j = idx & 511;
    const int og  = b * 1024 + j;
    const int orr = og + 512;

    float gpre = b_g[j], rpre = b_r[j];
    #pragma unroll
    for (int s = 0; s < NSPLIT; s++) {
        gpre += d_part[s][og];
        rpre += d_part[s][orr];
    }

    float g = tanhf(gpre);
    g = fmaxf(g, 0.f);                      // relu(tanh)
    const float r  = tanhf(rpre);
    const float hl = h_last[idx];
    const float h  = g * r + (1.f - g) * hl;
    const float Hg = (g > 0.f) ? 1.f : 0.f;
    const float dg = (1.f - g * g) * Hg;
    const float dr = 1.f - r * r;
    const float delta = r - hl;
    const float a  = 1.f - g;
    const float cg = dg * delta;
    const float cr = dr * g;

    d_av[idx]  = a;
    d_cgv[idx] = cg;
    d_crv[idx] = cr;
    d_hv[idx]  = h;

    out_h[idx]   = h;
    out_ebg[idx] = e_b_g[idx] * a + cg;
    out_ebr[idx] = e_b_r[idx] * a + cr;

    const int cnt = __popc(__ballot_sync(0xffffffffu, g > 0.f));
    if ((threadIdx.x & 31) == 0) scnt[threadIdx.x >> 5] = cnt;
    __syncthreads();
    if (threadIdx.x == 0) {
        int t = 0;
        #pragma unroll
        for (int w = 0; w < 8; w++) t += scnt[w];
        d_cnt[blockIdx.x] = t;
    }
}

// ---------------------------------------------------------------------------
// Paired full-K GEMM for p & o with fused activation epilogue.
// One CTA owns a 64m x 64j block and computes BOTH p and o pre-activations
// over the full K=1024 (x | d_hv), then writes out = sigmoid(o)*tanh(p).
// ---------------------------------------------------------------------------
__device__ __forceinline__ void gemm2_body(
    const float* __restrict__ x,
    const float* __restrict__ w_px, const float* __restrict__ w_ph,
    const float* __restrict__ w_ox, const float* __restrict__ w_oh,
    const float* __restrict__ b_p,  const float* __restrict__ b_o,
    float* __restrict__ out, int bx, int tid)
{
    __shared__ float As[16][68];
    __shared__ float Ps[16][68];
    __shared__ float Os[16][68];

    const int j0 = (bx & 7) * 64;
    const int m0 = (bx >> 3) * 64;

    const int lm  = tid & 63;
    const int lk4 = (tid >> 6) << 2;
    const int tx  = tid & 15;
    const int ty  = tid >> 4;

    float accP[4][4], accO[4][4];
    #pragma unroll
    for (int i = 0; i < 4; i++)
        #pragma unroll
        for (int j = 0; j < 4; j++) { accP[i][j] = 0.f; accO[i][j] = 0.f; }

    float4 av = *(const float4*)(x    + (m0 + lm) * 512 + lk4);
    float4 pv = *(const float4*)(w_px + (j0 + lm) * 512 + lk4);
    float4 ov = *(const float4*)(w_ox + (j0 + lm) * 512 + lk4);

    for (int kt = 0; kt < 1024; kt += 16) {
        __syncthreads();
        As[lk4 + 0][lm] = av.x; As[lk4 + 1][lm] = av.y;
        As[lk4 + 2][lm] = av.z; As[lk4 + 3][lm] = av.w;
        Ps[lk4 + 0][lm] = pv.x; Ps[lk4 + 1][lm] = pv.y;
        Ps[lk4 + 2][lm] = pv.z; Ps[lk4 + 3][lm] = pv.w;
        Os[lk4 + 0][lm] = ov.x; Os[lk4 + 1][lm] = ov.y;
        Os[lk4 + 2][lm] = ov.z; Os[lk4 + 3][lm] = ov.w;
        __syncthreads();

        const int kn = kt + 16;
        if (kn < 1024) {                      // prefetch next tile
            const int kk2 = (kn < 512) ? kn : (kn - 512);
            const float* An = (kn < 512) ? x    : d_hv;
            const float* Pn = (kn < 512) ? w_px : w_ph;
            const float* On = (kn < 512) ? w_ox : w_oh;
            av = *(const float4*)(An + (m0 + lm) * 512 + kk2 + lk4);
            pv = *(const float4*)(Pn + (j0 + lm) * 512 + kk2 + lk4);
            ov = *(const float4*)(On + (j0 + lm) * 512 + kk2 + lk4);
        }

        #pragma unroll
        for (int kk = 0; kk < 16; kk++) {
            const float4 a = *(const float4*)&As[kk][ty << 2];
            const float4 p = *(const float4*)&Ps[kk][tx << 2];
            const float4 o = *(const float4*)&Os[kk][tx << 2];
            accP[0][0] = fmaf(a.x, p.x, accP[0][0]);
            accP[0][1] = fmaf(a.x, p.y, accP[0][1]);
            accP[0][2] = fmaf(a.x, p.z, accP[0][2]);
            accP[0][3] = fmaf(a.x, p.w, accP[0][3]);
            accP[1][0] = fmaf(a.y, p.x, accP[1][0]);
            accP[1][1] = fmaf(a.y, p.y, accP[1][1]);
            accP[1][2] = fmaf(a.y, p.z, accP[1][2]);
            accP[1][3] = fmaf(a.y, p.w, accP[1][3]);
            accP[2][0] = fmaf(a.z, p.x, accP[2][0]);
            accP[2][1] = fmaf(a.z, p.y, accP[2][1]);
            accP[2][2] = fmaf(a.z, p.z, accP[2][2]);
            accP[2][3] = fmaf(a.z, p.w, accP[2][3]);
            accP[3][0] = fmaf(a.w, p.x, accP[3][0]);
            accP[3][1] = fmaf(a.w, p.y, accP[3][1]);
            accP[3][2] = fmaf(a.w, p.z, accP[3][2]);
            accP[3][3] = fmaf(a.w, p.w, accP[3][3]);
            accO[0][0] = fmaf(a.x, o.x, accO[0][0]);
            accO[0][1] = fmaf(a.x, o.y, accO[0][1]);
            accO[0][2] = fmaf(a.x, o.z, accO[0][2]);
            accO[0][3] = fmaf(a.x, o.w, accO[0][3]);
            accO[1][0] = fmaf(a.y, o.x, accO[1][0]);
            accO[1][1] = fmaf(a.y, o.y, accO[1][1]);
            accO[1][2] = fmaf(a.y, o.z, accO[1][2]);
            accO[1][3] = fmaf(a.y, o.w, accO[1][3]);
            accO[2][0] = fmaf(a.z, o.x, accO[2][0]);
            accO[2][1] = fmaf(a.z, o.y, accO[2][1]);
            accO[2][2] = fmaf(a.z, o.z, accO[2][2]);
            accO[2][3] = fmaf(a.z, o.w, accO[2][3]);
            accO[3][0] = fmaf(a.w, o.x, accO[3][0]);
            accO[3][1] = fmaf(a.w, o.y, accO[3][1]);
            accO[3][2] = fmaf(a.w, o.z, accO[3][2]);
            accO[3][3] = fmaf(a.w, o.w, accO[3][3]);
        }
    }

    #pragma unroll
    for (int i = 0; i < 4; i++) {
        float4 v;
        #pragma unroll
        for (int j = 0; j < 4; j++) {
            const int jj = j0 + (tx << 2) + j;
            const float pre_p = accP[i][j] + b_p[jj];
            const float pre_o = accO[i][j] + b_o[jj];
            const float pval  = tanhf(pre_p);
            const float oval  = 1.f / (1.f + expf(-pre_o));
            ((float*)&v)[j] = oval * pval;
        }
        *(float4*)(out + (m0 + (ty << 2) + i) * 512 + j0 + (tx << 2)) = v;
    }
}

// Trace row update body: idx in [0, 8388608)
__device__ __forceinline__ void trace_body(
    int idx,
    const float* __restrict__ x,  const float* __restrict__ hl,
    const float* __restrict__ egx, const float* __restrict__ egh,
    const float* __restrict__ erx, const float* __restrict__ erh,
    float* __restrict__ ogx, float* __restrict__ ogh,
    float* __restrict__ orx, float* __restrict__ orh)
{
    const int i   = (idx & 127) << 2;
    const int bj  = idx >> 7;
    const int b   = bj >> 9;

    const float a  = __ldg(&d_av[bj]);
    const float cg = __ldg(&d_cgv[bj]);
    const float cr = __ldg(&d_crv[bj]);

    const float4 xv = *(const float4*)(x  + (b << 9) + i);
    const float4 hv = *(const float4*)(hl + (b << 9) + i);
    const int off = (bj << 9) + i;

    float4 e, t;

    e = *(const float4*)(egx + off);
    t.x = e.x * a + cg * xv.x; t.y = e.y * a + cg * xv.y;
    t.z = e.z * a + cg * xv.z; t.w = e.w * a + cg * xv.w;
    *(float4*)(ogx + off) = t;

    e = *(const float4*)(egh + off);
    t.x = e.x * a + cg * hv.x; t.y = e.y * a + cg * hv.y;
    t.z = e.z * a + cg * hv.z; t.w = e.w * a + cg * hv.w;
    *(float4*)(ogh + off) = t;

    e = *(const float4*)(erx + off);
    t.x = e.x * a + cr * xv.x; t.y = e.y * a + cr * xv.y;
    t.z = e.z * a + cr * xv.z; t.w = e.w * a + cr * xv.w;
    *(float4*)(orx + off) = t;

    e = *(const float4*)(erh + off);
    t.x = e.x * a + cr * hv.x; t.y = e.y * a + cr * hv.y;
    t.z = e.z * a + cr * hv.z; t.w = e.w * a + cr * hv.w;
    *(float4*)(orh + off) = t;
}

// ---------------------------------------------------------------------------
// Launch 3: FUSED kernel.
//   blocks [0, 16)                 : paired p/o GEMM, fused activation -> out
//   blocks [16, 16+32768)          : HBM-bound trace update
//   block  16+32768                : openings scalar from d_cnt
// ---------------------------------------------------------------------------
__global__ void __launch_bounds__(256) k_fused(
    const float* __restrict__ x,  const float* __restrict__ h_last,
    const float* __restrict__ w_px, const float* __restrict__ w_ph,
    const float* __restrict__ w_ox, const float* __restrict__ w_oh,
    const float* __restrict__ b_p,  const float* __restrict__ b_o,
    const float* __restrict__ egx, const float* __restrict__ egh,
    const float* __restrict__ erx, const float* __restrict__ erh,
    float* __restrict__ ogx, float* __restrict__ ogh,
    float* __restrict__ orx, float* __restrict__ orh,
    float* __restrict__ o_out, float* __restrict__ o_open)
{
    const int bx = blockIdx.x;
    if (bx < GEMM2_BLOCKS) {
        gemm2_body(x, w_px, w_ph, w_ox, w_oh, b_p, b_o, o_out, bx, threadIdx.x);
    } else if (bx < GEMM2_BLOCKS + TRACE_BLOCKS) {
        const int idx = (bx - GEMM2_BLOCKS) * 256 + threadIdx.x;
        trace_body(idx, x, h_last, egx, egh, erx, erh, ogx, ogh, orx, orh);
    } else {
        __shared__ int scnt[256];
        scnt[threadIdx.x] = d_cnt[threadIdx.x];
        __syncthreads();
        for (int st = 128; st > 0; st >>= 1) {
            if (threadIdx.x < st) scnt[threadIdx.x] += scnt[threadIdx.x + st];
            __syncthreads();
        }
        if (threadIdx.x == 0)
            o_open[0] = (float)scnt[0] * (1.f / (float)GATE_ELEMS);
    }
}

// ---------------------------------------------------------------------------
extern "C" void kernel_launch(void* const* d_in, const int* in_sizes, int n_in,
                              void* d_out, int out_size)
{
    const float* x      = (const float*)d_in[0];
    const float* h_last = (const float*)d_in[1];
    const float* w_gx   = (const float*)d_in[2];
    const float* w_gh   = (const float*)d_in[3];
    const float* b_g    = (const float*)d_in[4];
    const float* w_rx   = (const float*)d_in[5];
    const float* w_rh   = (const float*)d_in[6];
    const float* b_r    = (const float*)d_in[7];
    const float* w_px   = (const float*)d_in[8];
    const float* w_ph   = (const float*)d_in[9];
    const float* b_p    = (const float*)d_in[10];
    const float* w_ox   = (const float*)d_in[11];
    const float* w_oh   = (const float*)d_in[12];
    const float* b_o    = (const float*)d_in[13];
    const float* e_w_gx = (const float*)d_in[14];
    const float* e_w_gh = (const float*)d_in[15];
    const float* e_b_g  = (const float*)d_in[16];
    const float* e_w_rx = (const float*)d_in[17];
    const float* e_w_rh = (const float*)d_in[18];
    const float* e_b_r  = (const float*)d_in[19];

    float* out    = (float*)d_out;
    float* o_out  = out;                  // (128,512)
    float* o_h    = out + 65536;          // (128,512)
    float* o_egx  = out + 131072;         // (128,512,512)
    float* o_egh  = out + 33685504;       // (128,512,512)
    float* o_ebg  = out + 67239936;       // (128,512)
    float* o_erx  = out + 67305472;       // (128,512,512)
    float* o_erh  = out + 100859904;      // (128,512,512)
    float* o_ebr  = out + 134414336;      // (128,512)
    float* o_open = out + 134479872;      // scalar

    // g/r pre-activations (split-K=16 partials, 512 CTAs)
    k_gemm1<<<dim3(16, 2, NSPLIT), 256>>>(x, h_last, w_gx, w_gh, w_rx, w_rh);

    // gate math, h, e_b updates, per-block open counts
    k_gates<<<256, 256>>>(h_last, b_g, b_r, e_b_g, e_b_r, o_h, o_ebg, o_ebr);

    // fused: paired p/o GEMM (+activations) + trace streamer + openings
    k_fused<<<GEMM2_BLOCKS + TRACE_BLOCKS + 1, 256>>>(
        x, h_last, w_px, w_ph, w_ox, w_oh, b_p, b_o,
        e_w_gx, e_w_gh, e_w_rx, e_w_rh,
        o_egx, o_egh, o_erx, o_erh,
        o_out, o_open);
}